// round 17
// baseline (speedup 1.0000x reference)
#include <cuda_runtime.h>
#include <cuda_fp16.h>
#include <math.h>
#include <stdint.h>

// ---------------------------------------------------------------------------
// GTN: H = diag(s) * HA * (HB*HB2), union-sparse pattern, fp16 dense M.
// Round 17 = round-16 + k_fill occupancy fix:
//  - softmax weights read from SMEM in the nz path (-30 regs/thread)
//  - 512 threads, 4 cols/thread, loads hoisted (no loop) -> ~75% occupancy
//  -> pipeline: k_fill(+transpose) -> k_M -> k_spmm(+head). 3 launches.
// Output: y[512*8] | all_Ws[3*2*5] | H[2*2048*2048]
// ---------------------------------------------------------------------------

#define NN    2048
#define NE    5
#define NC    2
#define CAP   256
#define NT    512
#define XD    512
#define WOUT  128
#define NCLS  8

#define Y_OFF  0
#define WS_OFF (NT * NCLS)
#define H_OFF  (WS_OFF + 3 * NC * NE)   // 4126 floats (8B aligned)

#define TR_BLOCKS 32                    // transpose blocks appended to k_fill

// ------------------------- static device scratch ---------------------------
__device__ int     g_cnt[NN];
__device__ int     g_cols[NN * CAP];
__device__ float   g_hav [NC][NN * CAP];
__device__ float   g_hbv [NC][NN * CAP];
__device__ __align__(16) int2 g_pb [NN * CAP];   // {col, HB packed half2 bits}
__device__ __align__(16) int2 g_pb2[NN * CAP];   // {col, HB2 packed half2 bits}
__device__ float   g_rB  [NC][NN];
__device__ float   g_rB2 [NC][NN];
__device__ float   g_rM  [NC][NN];
__device__ float   g_deg0[NC][NN];
__device__ __align__(16) __half2 g_Mi[NN][NN];   // M interleaved {c0,c1}, 16.8 MB
__device__ float   g_gwT[XD][WOUT];

// ------------------------------ helpers ------------------------------------
__device__ __forceinline__ float warpSum(float v) {
    #pragma unroll
    for (int o = 16; o > 0; o >>= 1) v += __shfl_down_sync(0xffffffffu, v, o);
    return v;
}
__device__ __forceinline__ __half2 bits2h2(int b) {
    __half2 h; *reinterpret_cast<int*>(&h) = b; return h;
}

// ---- kernel 1: pattern + values + rowsums + softmax + (transpose blocks) --
__global__ void __launch_bounds__(512) k_fill(const float* __restrict__ A,
                       const float* __restrict__ w1, const float* __restrict__ w2,
                       const float* __restrict__ w3, float* __restrict__ out_ws,
                       const float* __restrict__ gw) {
    int i = blockIdx.x;
    int tid = threadIdx.x;
    // ---- absorbed transpose blocks (independent of fill work) ----
    if (i >= NN) {
        int tb = i - NN;
        #pragma unroll
        for (int r = 0; r < 4; r++) {
            int idx = tb * 2048 + r * 512 + tid;
            int jj = idx / XD, kk = idx % XD;
            g_gwT[kk][jj] = gw[idx];
        }
        return;
    }
    __shared__ float ssm[3][NC][NE];
    __shared__ float srb[NC], srb2[NC];
    __shared__ int scnt;
    if (tid == 0) scnt = 0;
    if (tid < NC) { srb[tid] = 0.f; srb2[tid] = 0.f; }
    if (tid < 3 * NC) {
        int m = tid / NC, c = tid % NC;
        const float* w = (m == 0 ? w1 : (m == 1 ? w2 : w3)) + c * NE;
        float mx = w[0];
        #pragma unroll
        for (int e = 1; e < NE; e++) mx = fmaxf(mx, w[e]);
        float ex[NE], s = 0.f;
        #pragma unroll
        for (int e = 0; e < NE; e++) { ex[e] = expf(w[e] - mx); s += ex[e]; }
        float inv = 1.f / s;
        #pragma unroll
        for (int e = 0; e < NE; e++) {
            float v = ex[e] * inv;
            ssm[m][c][e] = v;
            if (i == 0) out_ws[m * NC * NE + c * NE + e] = v;
        }
    }
    __syncthreads();
    // each thread owns exactly 4 columns; all 5 row-loads hoisted (MLP=5)
    const int jb = tid * 4;
    float4 av[NE];
    #pragma unroll
    for (int e = 0; e < NE; e++)
        av[e] = *reinterpret_cast<const float4*>(
            A + (size_t)e * NN * NN + (size_t)i * NN + jb);
    #pragma unroll
    for (int q = 0; q < 4; q++) {
        float a[NE];
        a[0] = q == 0 ? av[0].x : q == 1 ? av[0].y : q == 2 ? av[0].z : av[0].w;
        a[1] = q == 0 ? av[1].x : q == 1 ? av[1].y : q == 2 ? av[1].z : av[1].w;
        a[2] = q == 0 ? av[2].x : q == 1 ? av[2].y : q == 2 ? av[2].z : av[2].w;
        a[3] = q == 0 ? av[3].x : q == 1 ? av[3].y : q == 2 ? av[3].z : av[3].w;
        a[4] = q == 0 ? av[4].x : q == 1 ? av[4].y : q == 2 ? av[4].z : av[4].w;
        bool nz = (a[0] != 0.f) | (a[1] != 0.f) | (a[2] != 0.f) |
                  (a[3] != 0.f) | (a[4] != 0.f);
        if (nz) {
            int slot = atomicAdd(&scnt, 1);
            if (slot < CAP) {
                int p = i * CAP + slot;
                int j = jb + q;
                g_cols[p] = j;
                float vb_[NC], vb2_[NC];
                #pragma unroll
                for (int c = 0; c < NC; c++) {
                    float va = 0.f, vb = 0.f, vb2 = 0.f;
                    #pragma unroll
                    for (int e = 0; e < NE; e++) {
                        va  += ssm[0][c][e] * a[e];   // smem reads: no reg cache
                        vb  += ssm[1][c][e] * a[e];
                        vb2 += ssm[2][c][e] * a[e];
                    }
                    g_hav[c][p] = va; g_hbv[c][p] = vb;
                    vb_[c] = vb; vb2_[c] = vb2;
                    atomicAdd(&srb[c],  vb);
                    atomicAdd(&srb2[c], vb2);
                }
                __half2 hb  = __floats2half2_rn(vb_[0],  vb_[1]);
                __half2 hb2 = __floats2half2_rn(vb2_[0], vb2_[1]);
                g_pb [p] = make_int2(j, *reinterpret_cast<int*>(&hb));
                g_pb2[p] = make_int2(j, *reinterpret_cast<int*>(&hb2));
            }
        }
    }
    __syncthreads();
    if (tid < NC) { g_rB[tid][i] = srb[tid]; g_rB2[tid][i] = srb2[tid]; }
    if (tid == 0) {
        int cnt = min(scnt, CAP);
        g_cnt[i] = cnt;
        // pad to even for k_M's paired LDG.128 inner loop (zero no-op entry)
        if (cnt < CAP && (cnt & 1)) g_pb2[i * CAP + cnt] = make_int2(0, 0);
    }
}

// ---- kernel 2: M = HB @ HB2 + per-row deg0/rM (k_deg folded in) -----------
__global__ void k_M() {
    int k = blockIdx.x;
    __shared__ __align__(16) __half2 acc[NN];         // 8 KB, {c0,c1} per col
    __shared__ int  sl[CAP];
    __shared__ int  shb[CAP];
    __shared__ int  snp[CAP];
    __shared__ float sred[8][4];
    for (int j = threadIdx.x; j < NN; j += blockDim.x)
        acc[j] = __float2half2_rn(0.f);
    int cnt = g_cnt[k];
    int tid = threadIdx.x;
    float d0 = 0.f, d1 = 0.f, m0 = 0.f, m1 = 0.f;
    if (tid < cnt) {
        int p = k * CAP + tid;
        int2 pe = g_pb[p];
        sl[tid]  = pe.x;
        shb[tid] = pe.y;
        snp[tid] = (g_cnt[pe.x] + 1) >> 1;
        int col = pe.x;
        d0 = g_hav[0][p] * g_rB[0][col];
        d1 = g_hav[1][p] * g_rB[1][col];
        m0 = g_hbv[0][p] * g_rB2[0][col];
        m1 = g_hbv[1][p] * g_rB2[1][col];
    }
    d0 = warpSum(d0); d1 = warpSum(d1); m0 = warpSum(m0); m1 = warpSum(m1);
    int warp = tid >> 5, lane = tid & 31;
    if (lane == 0) { sred[warp][0] = d0; sred[warp][1] = d1; sred[warp][2] = m0; sred[warp][3] = m1; }
    __syncthreads();
    if (tid == 0) {
        float v0 = 0, v1 = 0, v2 = 0, v3 = 0;
        #pragma unroll
        for (int q = 0; q < 8; q++) { v0 += sred[q][0]; v1 += sred[q][1]; v2 += sred[q][2]; v3 += sred[q][3]; }
        g_deg0[0][k] = v0; g_deg0[1][k] = v1; g_rM[0][k] = v2; g_rM[1][k] = v3;
    }
    for (int pi = warp; pi < cnt; pi += 8) {
        int l = sl[pi];
        __half2 hb = bits2h2(shb[pi]);
        int npairs = snp[pi];
        const int4* src = reinterpret_cast<const int4*>(&g_pb2[l * CAP]);
        for (int t = lane; t < npairs; t += 32) {
            int4 qq = src[t];                         // 2 entries, 1 LDG.128
            atomicAdd(&acc[qq.x], __hmul2(hb, bits2h2(qq.y)));
            atomicAdd(&acc[qq.z], __hmul2(hb, bits2h2(qq.w)));
        }
    }
    __syncthreads();
    uint4* dst = reinterpret_cast<uint4*>(&g_Mi[k][0]);
    const uint4* s4 = reinterpret_cast<const uint4*>(acc);
    for (int t = threadIdx.x; t < NN / 4; t += blockDim.x)
        dst[t] = s4[t];
}

// ---- kernel 3: H = diag(scale)*HA@M  (+ absorbed head blocks) -------------
__global__ void __launch_bounds__(512) k_spmm(float* __restrict__ H,
        const float* __restrict__ Xm, const float* __restrict__ gcn_b,
        const float* __restrict__ lin_w, const float* __restrict__ lin_b,
        const int* __restrict__ tx, float* __restrict__ y) {
    const int i = blockIdx.x;
    const int tid = threadIdx.x;
    // ---- absorbed classification-head blocks ----
    if (i >= NN) {
        int t = i - NN;
        int row = tx[t];
        __shared__ float xr[XD];
        __shared__ float h[WOUT];
        for (int k = tid; k < XD; k += blockDim.x)
            xr[k] = Xm[(size_t)row * XD + k];
        __syncthreads();
        if (tid < WOUT) {
            float acc = gcn_b[tid];
            #pragma unroll 8
            for (int k = 0; k < XD; k++) acc += g_gwT[k][tid] * xr[k];
            h[tid] = fmaxf(acc, 0.f);
        }
        __syncthreads();
        if (tid < NCLS) {
            float acc2 = lin_b[tid];
            #pragma unroll 4
            for (int m = 0; m < WOUT; m++)
                acc2 += (lin_w[tid * (NC * WOUT) + m] + lin_w[tid * (NC * WOUT) + WOUT + m]) * h[m];
            y[t * NCLS + tid] = acc2;
        }
        return;
    }
    const int j0 = tid * 4;
    __shared__ int    scol[CAP];
    __shared__ float2 sw[CAP];
    __shared__ float sred[16][2];
    __shared__ float ssc[2];
    const int cnt = g_cnt[i];
    float t0 = 0.f, t1 = 0.f;
    if (tid < cnt) {
        int p = i * CAP + tid;
        int col = g_cols[p];
        float2 wv = make_float2(g_hav[0][p], g_hav[1][p]);
        scol[tid] = col;
        sw[tid]   = wv;
        t0 = wv.x * g_rM[0][col];
        t1 = wv.y * g_rM[1][col];
    }
    t0 = warpSum(t0); t1 = warpSum(t1);
    const int warp = tid >> 5, lane = tid & 31;
    if (lane == 0) { sred[warp][0] = t0; sred[warp][1] = t1; }
    __syncthreads();
    if (tid == 0) {
        float tt0 = 0, tt1 = 0;
        #pragma unroll
        for (int q = 0; q < 16; q++) { tt0 += sred[q][0]; tt1 += sred[q][1]; }
        float dg0 = g_deg0[0][i];
        float d0 = (dg0 > 0.f) ? (1.f / sqrtf(dg0)) : 0.f;
        float dg1 = d0 * tt0;
        float d1 = (dg1 > 0.f) ? (1.f / sqrtf(dg1)) : 0.f;
        ssc[0] = d0 * d1;
        dg0 = g_deg0[1][i];
        d0 = (dg0 > 0.f) ? (1.f / sqrtf(dg0)) : 0.f;
        dg1 = d0 * tt1;
        d1 = (dg1 > 0.f) ? (1.f / sqrtf(dg1)) : 0.f;
        ssc[1] = d0 * d1;
    }
    __syncthreads();
    float a00 = 0, a01 = 0, a02 = 0, a03 = 0;   // channel 0
    float a10 = 0, a11 = 0, a12 = 0, a13 = 0;   // channel 1
    #define ACCUM(mv, wv) do {                                    \
        float2 f0 = __half22float2(bits2h2((int)(mv).x));         \
        float2 f1 = __half22float2(bits2h2((int)(mv).y));         \
        float2 f2 = __half22float2(bits2h2((int)(mv).z));         \
        float2 f3 = __half22float2(bits2h2((int)(mv).w));         \
        a00 += (wv).x * f0.x; a10 += (wv).y * f0.y;               \
        a01 += (wv).x * f1.x; a11 += (wv).y * f1.y;               \
        a02 += (wv).x * f2.x; a12 += (wv).y * f2.y;               \
        a03 += (wv).x * f3.x; a13 += (wv).y * f3.y;               \
    } while (0)
    int l = 0;
    for (; l + 8 <= cnt; l += 8) {
        uint4 m0 = *reinterpret_cast<const uint4*>(&g_Mi[scol[l + 0]][j0]);
        uint4 m1 = *reinterpret_cast<const uint4*>(&g_Mi[scol[l + 1]][j0]);
        uint4 m2 = *reinterpret_cast<const uint4*>(&g_Mi[scol[l + 2]][j0]);
        uint4 m3 = *reinterpret_cast<const uint4*>(&g_Mi[scol[l + 3]][j0]);
        uint4 m4 = *reinterpret_cast<const uint4*>(&g_Mi[scol[l + 4]][j0]);
        uint4 m5 = *reinterpret_cast<const uint4*>(&g_Mi[scol[l + 5]][j0]);
        uint4 m6 = *reinterpret_cast<const uint4*>(&g_Mi[scol[l + 6]][j0]);
        uint4 m7 = *reinterpret_cast<const uint4*>(&g_Mi[scol[l + 7]][j0]);
        float2 w0 = sw[l + 0], w1 = sw[l + 1], w2 = sw[l + 2], w3 = sw[l + 3];
        float2 w4 = sw[l + 4], w5 = sw[l + 5], w6 = sw[l + 6], w7 = sw[l + 7];
        ACCUM(m0, w0); ACCUM(m1, w1); ACCUM(m2, w2); ACCUM(m3, w3);
        ACCUM(m4, w4); ACCUM(m5, w5); ACCUM(m6, w6); ACCUM(m7, w7);
    }
    for (; l < cnt; l++) {
        uint4 m0 = *reinterpret_cast<const uint4*>(&g_Mi[scol[l]][j0]);
        float2 w0 = sw[l];
        ACCUM(m0, w0);
    }
    #undef ACCUM
    const float sc0 = ssc[0];
    const float sc1 = ssc[1];
    float2* o0 = reinterpret_cast<float2*>(&H[(size_t)0 * NN * NN + (size_t)i * NN + j0]);
    float2* o1 = reinterpret_cast<float2*>(&H[(size_t)1 * NN * NN + (size_t)i * NN + j0]);
    o0[0] = make_float2(sc0 * a00, sc0 * a01);
    o0[1] = make_float2(sc0 * a02, sc0 * a03);
    o1[0] = make_float2(sc1 * a10, sc1 * a11);
    o1[1] = make_float2(sc1 * a12, sc1 * a13);
}

// ------------------------------ launch -------------------------------------
extern "C" void kernel_launch(void* const* d_in, const int* in_sizes, int n_in,
                              void* d_out, int out_size) {
    const float* A     = (const float*)d_in[0];
    const float* X     = (const float*)d_in[1];
    const float* w01   = (const float*)d_in[2];
    const float* w02   = (const float*)d_in[3];
    const float* w11   = (const float*)d_in[4];
    const float* gcn_w = (const float*)d_in[5];
    const float* gcn_b = (const float*)d_in[6];
    const float* lin_w = (const float*)d_in[7];
    const float* lin_b = (const float*)d_in[8];
    const int*   tx    = (const int*)d_in[9];
    float* out = (float*)d_out;

    k_fill<<<NN + TR_BLOCKS, 512>>>(A, w01, w02, w11, out + WS_OFF, gcn_w);
    k_M<<<NN, 256>>>();
    k_spmm<<<NN + NT, 512>>>(out + H_OFF, X, gcn_b, lin_w, lin_b, tx, out + Y_OFF);
}